// round 3
// baseline (speedup 1.0000x reference)
#include <cuda_runtime.h>
#include <cstdint>
#include <cstddef>

#define NNODES 100000
#define DD 128

// Scratch, float4-typed => guaranteed 16B alignment (required by red.global.add.v4.f32).
__device__ float4 g_agg[(size_t)NNODES * (DD / 4)];
__device__ float4 g_h[(size_t)NNODES * (DD / 4)];

// ---------------------------------------------------------------------------
// agg = x   (the (1+eps)*x term with eps=0; scatter adds on top of this)
// ---------------------------------------------------------------------------
__global__ void copy_x_kernel(const float4* __restrict__ x, float4* __restrict__ agg, int n4) {
    int i = blockIdx.x * blockDim.x + threadIdx.x;
    if (i < n4) agg[i] = x[i];
}

// ---------------------------------------------------------------------------
// Scatter-add: one warp per edge, lane l owns float4 l (128 floats / edge).
// Indices are int32 (harness downcasts int64). Bounds-guarded so a dtype
// surprise yields wrong numbers (visible rel_err) instead of an IMA.
// ---------------------------------------------------------------------------
__global__ void scatter_add_kernel(const float4* __restrict__ x,
                                   const int* __restrict__ ei,
                                   float4* __restrict__ agg, int E, int N) {
    int gid = blockIdx.x * blockDim.x + threadIdx.x;
    int e = gid >> 5;
    int lane = gid & 31;
    if (e >= E) return;
    int src = ei[e];            // warp-uniform load
    int dst = ei[E + e];
    if ((unsigned)src >= (unsigned)N || (unsigned)dst >= (unsigned)N) return;
    float4 v = x[(size_t)src * 32 + lane];
    float4* p = agg + (size_t)dst * 32 + lane;
    asm volatile("red.global.add.v4.f32 [%0], {%1, %2, %3, %4};"
                 :: "l"(p), "f"(v.x), "f"(v.y), "f"(v.z), "f"(v.w)
                 : "memory");
}

// ---------------------------------------------------------------------------
// C[M,128] = act(A[M,128] @ W[128,128] + bias)
// Block: 256 threads, tile 128 rows x 128 cols, 8x8 register microtile.
// As padded to stride 130 so per-k a_frag reads are bank-conflict-free.
// ---------------------------------------------------------------------------
#define AS_STRIDE 130
#define GEMM_SMEM ((128 * AS_STRIDE + 128 * 128) * 4)

__global__ void __launch_bounds__(256, 1)
gemm128_kernel(const float* __restrict__ A, const float* __restrict__ W,
               const float* __restrict__ bias, float* __restrict__ C,
               int M, int do_relu) {
    extern __shared__ float sm[];
    float* As = sm;                       // [128][130]
    float* Ws = sm + 128 * AS_STRIDE;     // [128][128] row-major (k-major)

    int t = threadIdx.x;
    int row0 = blockIdx.x << 7;

    // Load W (64KB) into smem, float4-vectorized.
    const float4* Wv = (const float4*)W;
    float4* Wsv = (float4*)Ws;
#pragma unroll
    for (int i = 0; i < 16; i++) Wsv[t + 256 * i] = Wv[t + 256 * i];

    // Load A tile (128 rows x 128 cols) into smem with padded stride.
#pragma unroll
    for (int i = 0; i < 16; i++) {
        int f = t + 256 * i;          // float4 index: 32 float4 per row
        int r = f >> 5, c4 = f & 31;
        float4 v = make_float4(0.f, 0.f, 0.f, 0.f);
        int gr = row0 + r;
        if (gr < M) v = ((const float4*)A)[(size_t)gr * 32 + c4];
        float2* d = (float2*)(As + r * AS_STRIDE + c4 * 4);
        d[0] = make_float2(v.x, v.y);
        d[1] = make_float2(v.z, v.w);
    }
    __syncthreads();

    int ty = t >> 4, tx = t & 15;     // 16x16 thread grid, 8x8 microtile
    float acc[8][8];
#pragma unroll
    for (int i = 0; i < 8; i++)
#pragma unroll
        for (int j = 0; j < 8; j++) acc[i][j] = 0.f;

    const float* arow = As + (ty * 8) * AS_STRIDE;
    const float* wcol = Ws + tx * 8;

#pragma unroll 4
    for (int k = 0; k < 128; k++) {
        float a[8], b[8];
#pragma unroll
        for (int i = 0; i < 8; i++) a[i] = arow[i * AS_STRIDE + k];
        float4 b0 = *(const float4*)(wcol + k * 128);
        float4 b1 = *(const float4*)(wcol + k * 128 + 4);
        b[0] = b0.x; b[1] = b0.y; b[2] = b0.z; b[3] = b0.w;
        b[4] = b1.x; b[5] = b1.y; b[6] = b1.z; b[7] = b1.w;
#pragma unroll
        for (int i = 0; i < 8; i++)
#pragma unroll
            for (int j = 0; j < 8; j++)
                acc[i][j] = fmaf(a[i], b[j], acc[i][j]);
    }

    // Epilogue: bias + optional relu, float4 stores.
    float bb[8];
    float4 bv0 = *(const float4*)(bias + tx * 8);
    float4 bv1 = *(const float4*)(bias + tx * 8 + 4);
    bb[0] = bv0.x; bb[1] = bv0.y; bb[2] = bv0.z; bb[3] = bv0.w;
    bb[4] = bv1.x; bb[5] = bv1.y; bb[6] = bv1.z; bb[7] = bv1.w;

#pragma unroll
    for (int i = 0; i < 8; i++) {
        int gr = row0 + ty * 8 + i;
        if (gr < M) {
            float o[8];
#pragma unroll
            for (int j = 0; j < 8; j++) {
                o[j] = acc[i][j] + bb[j];
                if (do_relu) o[j] = fmaxf(o[j], 0.f);
            }
            float4* outp = (float4*)(C + (size_t)gr * 128 + tx * 8);
            outp[0] = make_float4(o[0], o[1], o[2], o[3]);
            outp[1] = make_float4(o[4], o[5], o[6], o[7]);
        }
    }
}

// ---------------------------------------------------------------------------
extern "C" void kernel_launch(void* const* d_in, const int* in_sizes, int n_in,
                              void* d_out, int out_size) {
    const float* x  = (const float*)d_in[0];
    const int*   ei = (const int*)d_in[1];      // int64 in reference, int32 from harness
    const float* W1 = (const float*)d_in[2];
    const float* b1 = (const float*)d_in[3];
    const float* W2 = (const float*)d_in[4];
    const float* b2 = (const float*)d_in[5];
    float* out = (float*)d_out;

    int M = in_sizes[0] / DD;        // 100000
    int E = in_sizes[1] / 2;         // 1600000

    float4* agg_ptr = nullptr;
    float4* h_ptr   = nullptr;
    cudaGetSymbolAddress((void**)&agg_ptr, g_agg);
    cudaGetSymbolAddress((void**)&h_ptr, g_h);
    cudaFuncSetAttribute(gemm128_kernel,
                         cudaFuncAttributeMaxDynamicSharedMemorySize, GEMM_SMEM);

    // 1) agg = x
    int n4 = M * (DD / 4);
    copy_x_kernel<<<(n4 + 255) / 256, 256>>>((const float4*)x, agg_ptr, n4);

    // 2) agg += scatter(x[src] -> dst)
    long long total_threads = (long long)E * 32;
    int sblocks = (int)((total_threads + 255) / 256);
    scatter_add_kernel<<<sblocks, 256>>>((const float4*)x, ei, agg_ptr, E, M);

    // 3) h = relu(agg @ W1 + b1)
    int gblocks = (M + 127) / 128;
    gemm128_kernel<<<gblocks, 256, GEMM_SMEM>>>((const float*)agg_ptr, W1, b1,
                                                (float*)h_ptr, M, 1);

    // 4) out = h @ W2 + b2
    gemm128_kernel<<<gblocks, 256, GEMM_SMEM>>>((const float*)h_ptr, W2, b2, out, M, 0);
}

// round 6
// speedup vs baseline: 1.1738x; 1.1738x over previous
#include <cuda_runtime.h>
#include <cuda_bf16.h>
#include <cstdint>
#include <cstddef>

#define NNODES 100000
#define DD 128

// Scratch (16B-aligned types).
__device__ float4 g_agg[(size_t)NNODES * (DD / 4)];
__device__ float4 g_h[(size_t)NNODES * (DD / 4)];

// Row stride for bf16 [*][k=128] tiles: 256B data + 16B pad => conflict-free frags.
#define BSTRIDE 272
#define WIMG_BYTES (128 * BSTRIDE)
// W images: [W1hi|W1lo|W2hi|W2lo]
__device__ uint4 g_wimg[4 * WIMG_BYTES / 16];

// ---------------------------------------------------------------------------
// agg = x
// ---------------------------------------------------------------------------
__global__ void copy_x_kernel(const float4* __restrict__ x, float4* __restrict__ agg, int n4) {
    int i = blockIdx.x * blockDim.x + threadIdx.x;
    if (i < n4) agg[i] = x[i];
}

// ---------------------------------------------------------------------------
// Scatter-add: one warp per edge, red.global.add.v4.f32.
// ---------------------------------------------------------------------------
__global__ void scatter_add_kernel(const float4* __restrict__ x,
                                   const int* __restrict__ ei,
                                   float4* __restrict__ agg, int E, int N) {
    int gid = blockIdx.x * blockDim.x + threadIdx.x;
    int e = gid >> 5;
    int lane = gid & 31;
    if (e >= E) return;
    int src = ei[e];
    int dst = ei[E + e];
    if ((unsigned)src >= (unsigned)N || (unsigned)dst >= (unsigned)N) return;
    float4 v = x[(size_t)src * 32 + lane];
    float4* p = agg + (size_t)dst * 32 + lane;
    asm volatile("red.global.add.v4.f32 [%0], {%1, %2, %3, %4};"
                 :: "l"(p), "f"(v.x), "f"(v.y), "f"(v.z), "f"(v.w) : "memory");
}

// ---------------------------------------------------------------------------
// Pre-convert W (fp32 [k=128][n=128] row-major) into bf16 hi/lo images laid
// out [n][k] with BSTRIDE row stride (B operand, col-major for mma.row.col).
// ---------------------------------------------------------------------------
__global__ void prep_w_kernel(const float* __restrict__ W1, const float* __restrict__ W2,
                              unsigned char* __restrict__ img) {
    const float* W = blockIdx.x ? W2 : W1;
    unsigned char* hi = img + (size_t)blockIdx.x * 2 * WIMG_BYTES;
    unsigned char* lo = hi + WIMG_BYTES;
    for (int id = threadIdx.x; id < 16384; id += blockDim.x) {
        int k = id >> 7, n = id & 127;
        float v = W[id];
        __nv_bfloat16 h = __float2bfloat16(v);
        __nv_bfloat16 l = __float2bfloat16(v - __bfloat162float(h));
        *(__nv_bfloat16*)(hi + n * BSTRIDE + k * 2) = h;
        *(__nv_bfloat16*)(lo + n * BSTRIDE + k * 2) = l;
    }
}

// ---------------------------------------------------------------------------
// C[M,128] = act(A[M,128] @ W + bias) via mma.sync bf16 3-term compensation.
// 256 threads, M-tile 128, warp tile 32(m) x 64(n). K=128 smem-resident.
// ---------------------------------------------------------------------------
#define SM_AHI 0
#define SM_ALO (SM_AHI + 128 * BSTRIDE)
#define SM_BHI (SM_ALO + 128 * BSTRIDE)
#define SM_BLO (SM_BHI + 128 * BSTRIDE)
#define SM_BIAS (SM_BLO + 128 * BSTRIDE)
#define SM_TOTAL (SM_BIAS + 512)

__device__ __forceinline__ void mma_bf16(float* d, uint32_t a0, uint32_t a1, uint32_t a2,
                                         uint32_t a3, uint32_t b0, uint32_t b1) {
    asm volatile("mma.sync.aligned.m16n8k16.row.col.f32.bf16.bf16.f32 "
                 "{%0,%1,%2,%3}, {%4,%5,%6,%7}, {%8,%9}, {%0,%1,%2,%3};"
                 : "+f"(d[0]), "+f"(d[1]), "+f"(d[2]), "+f"(d[3])
                 : "r"(a0), "r"(a1), "r"(a2), "r"(a3), "r"(b0), "r"(b1));
}
__device__ __forceinline__ uint32_t lds_u32(const unsigned char* p) {
    return *(const uint32_t*)p;
}

__global__ void __launch_bounds__(256, 1)
mlp_mma_kernel(const float* __restrict__ A, const unsigned char* __restrict__ Wimg,
               const float* __restrict__ bias, float* __restrict__ C, int M, int do_relu) {
    extern __shared__ unsigned char sm[];
    int t = threadIdx.x, lane = t & 31, w = t >> 5;
    int wm = w >> 1, wn = w & 1;         // 4 m-warps x 2 n-warps
    int row0 = blockIdx.x << 7;

    // ---- Load W hi+lo image (2*WIMG contiguous) ----
    {
        const uint4* s = (const uint4*)Wimg;
        uint4* d = (uint4*)(sm + SM_BHI);
#pragma unroll
        for (int i = 0; i < (2 * WIMG_BYTES / 16) / 256; i++)
            d[t + 256 * i] = s[t + 256 * i];
    }
    // ---- Load A tile, split to bf16 hi/lo ----
#pragma unroll
    for (int i = 0; i < 16; i++) {
        int fid = t + 256 * i;           // 32 float4 per row
        int m = fid >> 5, c4 = fid & 31;
        int gr = row0 + m;
        float4 v = make_float4(0.f, 0.f, 0.f, 0.f);
        if (gr < M) v = ((const float4*)A)[(size_t)gr * 32 + c4];
        float f[4] = {v.x, v.y, v.z, v.w};
        uint32_t hp[2], lp[2];
#pragma unroll
        for (int j = 0; j < 2; j++) {
            __nv_bfloat16 h0 = __float2bfloat16(f[2 * j]);
            __nv_bfloat16 h1 = __float2bfloat16(f[2 * j + 1]);
            __nv_bfloat16 l0 = __float2bfloat16(f[2 * j] - __bfloat162float(h0));
            __nv_bfloat16 l1 = __float2bfloat16(f[2 * j + 1] - __bfloat162float(h1));
            hp[j] = (uint32_t)*(uint16_t*)&h0 | ((uint32_t)*(uint16_t*)&h1 << 16);
            lp[j] = (uint32_t)*(uint16_t*)&l0 | ((uint32_t)*(uint16_t*)&l1 << 16);
        }
        *(uint2*)(sm + SM_AHI + m * BSTRIDE + c4 * 8) = make_uint2(hp[0], hp[1]);
        *(uint2*)(sm + SM_ALO + m * BSTRIDE + c4 * 8) = make_uint2(lp[0], lp[1]);
    }
    if (t < 128) ((float*)(sm + SM_BIAS))[t] = bias[t];
    __syncthreads();

    float acc[2][8][4];
#pragma unroll
    for (int s = 0; s < 2; s++)
#pragma unroll
        for (int nt = 0; nt < 8; nt++)
#pragma unroll
            for (int r = 0; r < 4; r++) acc[s][nt][r] = 0.f;

    int qr = lane >> 2, qc = lane & 3;   // quad row/col

#pragma unroll
    for (int ks = 0; ks < 8; ks++) {
        int kb = ks * 32 + qc * 4;       // byte offset of this thread's k pair
        // A fragments: 2 m-subtiles x {hi,lo}
        uint32_t ah[2][4], al[2][4];
#pragma unroll
        for (int s = 0; s < 2; s++) {
            int r = wm * 32 + s * 16 + qr;
            const unsigned char* pa = sm + SM_AHI + r * BSTRIDE + kb;
            ah[s][0] = lds_u32(pa);
            ah[s][1] = lds_u32(pa + 8 * BSTRIDE);
            ah[s][2] = lds_u32(pa + 16);
            ah[s][3] = lds_u32(pa + 8 * BSTRIDE + 16);
            const unsigned char* pl = pa + (SM_ALO - SM_AHI);
            al[s][0] = lds_u32(pl);
            al[s][1] = lds_u32(pl + 8 * BSTRIDE);
            al[s][2] = lds_u32(pl + 16);
            al[s][3] = lds_u32(pl + 8 * BSTRIDE + 16);
        }
#pragma unroll
        for (int nt = 0; nt < 8; nt++) {
            int n = wn * 64 + nt * 8 + qr;
            const unsigned char* pb = sm + SM_BHI + n * BSTRIDE + kb;
            uint32_t bh0 = lds_u32(pb), bh1 = lds_u32(pb + 16);
            const unsigned char* pbl = pb + (SM_BLO - SM_BHI);
            uint32_t bl0 = lds_u32(pbl), bl1 = lds_u32(pbl + 16);
#pragma unroll
            for (int s = 0; s < 2; s++) {
                mma_bf16(acc[s][nt], ah[s][0], ah[s][1], ah[s][2], ah[s][3], bh0, bh1);
                mma_bf16(acc[s][nt], ah[s][0], ah[s][1], ah[s][2], ah[s][3], bl0, bl1);
                mma_bf16(acc[s][nt], al[s][0], al[s][1], al[s][2], al[s][3], bh0, bh1);
            }
        }
    }

    // ---- Epilogue: bias + relu, direct gmem stores ----
    const float* sbias = (const float*)(sm + SM_BIAS);
#pragma unroll
    for (int s = 0; s < 2; s++) {
#pragma unroll
        for (int nt = 0; nt < 8; nt++) {
            int n = wn * 64 + nt * 8 + qc * 2;
            float bb0 = sbias[n], bb1 = sbias[n + 1];
#pragma unroll
            for (int h = 0; h < 2; h++) {
                int gr = row0 + wm * 32 + s * 16 + qr + h * 8;
                if (gr < M) {
                    float o0 = acc[s][nt][2 * h] + bb0;
                    float o1 = acc[s][nt][2 * h + 1] + bb1;
                    if (do_relu) { o0 = fmaxf(o0, 0.f); o1 = fmaxf(o1, 0.f); }
                    *(float2*)(C + (size_t)gr * 128 + n) = make_float2(o0, o1);
                }
            }
        }
    }
}

// ---------------------------------------------------------------------------
extern "C" void kernel_launch(void* const* d_in, const int* in_sizes, int n_in,
                              void* d_out, int out_size) {
    const float* x  = (const float*)d_in[0];
    const int*   ei = (const int*)d_in[1];
    const float* W1 = (const float*)d_in[2];
    const float* b1 = (const float*)d_in[3];
    const float* W2 = (const float*)d_in[4];
    const float* b2 = (const float*)d_in[5];
    float* out = (float*)d_out;

    int M = in_sizes[0] / DD;        // 100000
    int E = in_sizes[1] / 2;         // 1600000

    float4* agg_ptr = nullptr;
    float4* h_ptr   = nullptr;
    unsigned char* wimg_ptr = nullptr;
    cudaGetSymbolAddress((void**)&agg_ptr, g_agg);
    cudaGetSymbolAddress((void**)&h_ptr, g_h);
    cudaGetSymbolAddress((void**)&wimg_ptr, g_wimg);
    cudaFuncSetAttribute(mlp_mma_kernel,
                         cudaFuncAttributeMaxDynamicSharedMemorySize, SM_TOTAL);

    // 1) agg = x
    int n4 = M * (DD / 4);
    copy_x_kernel<<<(n4 + 255) / 256, 256>>>((const float4*)x, agg_ptr, n4);

    // 2) W -> bf16 hi/lo images
    prep_w_kernel<<<2, 256>>>(W1, W2, wimg_ptr);

    // 3) agg += scatter(x[src] -> dst)
    long long total_threads = (long long)E * 32;
    int sblocks = (int)((total_threads + 255) / 256);
    scatter_add_kernel<<<sblocks, 256>>>((const float4*)x, ei, agg_ptr, E, M);

    // 4) h = relu(agg @ W1 + b1)
    int gblocks = (M + 127) / 128;
    mlp_mma_kernel<<<gblocks, 256, SM_TOTAL>>>((const float*)agg_ptr, wimg_ptr, b1,
                                               (float*)h_ptr, M, 1);

    // 5) out = h @ W2 + b2
    mlp_mma_kernel<<<gblocks, 256, SM_TOTAL>>>((const float*)h_ptr, wimg_ptr + 2 * WIMG_BYTES,
                                               b2, out, M, 0);
}